// round 1
// baseline (speedup 1.0000x reference)
#include <cuda_runtime.h>
#include <cuda_bf16.h>

// Scratch (no cudaMalloc allowed): column sums of weight, and bias sum.
__device__ float4 g_wsum4[2048];   // 8192 floats, 16B-aligned for float4 access
__device__ float  g_bias_sum;

// ---------------------------------------------------------------------------
// Kernel 0: zero the accumulators (graph replays must be deterministic).
// ---------------------------------------------------------------------------
__global__ void zero_kernel() {
    int i = blockIdx.x * blockDim.x + threadIdx.x;
    if (i < 2048) g_wsum4[i] = make_float4(0.f, 0.f, 0.f, 0.f);
    if (i == 0) g_bias_sum = 0.f;
}

// ---------------------------------------------------------------------------
// Kernel 1: w_sum[i] = sum over 8192 rows of weight[r, i].
// Layout: weight row-major [8192, 8192]. Thread t owns one float4 column
// group (4 columns). Block = 256 threads -> 1024 columns. grid.x = 8.
// grid.y row-chunks of ROWS_PER rows each; partial sums combined by atomicAdd.
// Loads are fully coalesced: 256 threads x 16B = 4KB contiguous per row.
// ---------------------------------------------------------------------------
#define ROWS_PER 64
__global__ void __launch_bounds__(256) wsum_kernel(const float4* __restrict__ w) {
    const int col4 = blockIdx.x * 256 + threadIdx.x;        // 0..2047
    const size_t row0 = (size_t)blockIdx.y * ROWS_PER;
    const float4* p = w + row0 * 2048 + col4;

    float4 a0 = make_float4(0.f, 0.f, 0.f, 0.f);
    float4 a1 = make_float4(0.f, 0.f, 0.f, 0.f);
    float4 a2 = make_float4(0.f, 0.f, 0.f, 0.f);
    float4 a3 = make_float4(0.f, 0.f, 0.f, 0.f);

    #pragma unroll 4
    for (int r = 0; r < ROWS_PER; r += 4) {
        float4 v0 = p[(size_t)(r + 0) * 2048];
        float4 v1 = p[(size_t)(r + 1) * 2048];
        float4 v2 = p[(size_t)(r + 2) * 2048];
        float4 v3 = p[(size_t)(r + 3) * 2048];
        a0.x += v0.x; a0.y += v0.y; a0.z += v0.z; a0.w += v0.w;
        a1.x += v1.x; a1.y += v1.y; a1.z += v1.z; a1.w += v1.w;
        a2.x += v2.x; a2.y += v2.y; a2.z += v2.z; a2.w += v2.w;
        a3.x += v3.x; a3.y += v3.y; a3.z += v3.z; a3.w += v3.w;
    }
    float sx = a0.x + a1.x + a2.x + a3.x;
    float sy = a0.y + a1.y + a2.y + a3.y;
    float sz = a0.z + a1.z + a2.z + a3.z;
    float sw = a0.w + a1.w + a2.w + a3.w;

    float* dst = (float*)&g_wsum4[col4];
    atomicAdd(dst + 0, sx);
    atomicAdd(dst + 1, sy);
    atomicAdd(dst + 2, sz);
    atomicAdd(dst + 3, sw);
}

// ---------------------------------------------------------------------------
// Kernel 2: bias_sum = sum(bias). Single block, 256 threads.
// ---------------------------------------------------------------------------
__global__ void __launch_bounds__(256) bias_kernel(const float4* __restrict__ bias4) {
    __shared__ float red[8];
    float acc = 0.f;
    for (int i = threadIdx.x; i < 2048; i += 256) {
        float4 v = bias4[i];
        acc += (v.x + v.y) + (v.z + v.w);
    }
    // warp reduce
    for (int o = 16; o > 0; o >>= 1) acc += __shfl_xor_sync(0xFFFFFFFFu, acc, o);
    if ((threadIdx.x & 31) == 0) red[threadIdx.x >> 5] = acc;
    __syncthreads();
    if (threadIdx.x == 0) {
        float s = 0.f;
        #pragma unroll
        for (int w = 0; w < 8; w++) s += red[w];
        g_bias_sum = s;
    }
}

// ---------------------------------------------------------------------------
// Kernel 3: out[b] = dot(x[b,:], w_sum) + bias_sum.  One block per row.
// x row = 8192 floats = 2048 float4; 256 threads -> 8 float4 each.
// w_sum stays hot in L2/L1 (32 KB).
// ---------------------------------------------------------------------------
__global__ void __launch_bounds__(256) dot_kernel(const float4* __restrict__ x,
                                                  float* __restrict__ out) {
    __shared__ float red[8];
    const size_t b = blockIdx.x;
    const float4* xr = x + b * 2048;

    float acc = 0.f;
    #pragma unroll 8
    for (int i = threadIdx.x; i < 2048; i += 256) {
        float4 xv = xr[i];
        float4 wv = g_wsum4[i];
        acc += xv.x * wv.x + xv.y * wv.y + xv.z * wv.z + xv.w * wv.w;
    }
    for (int o = 16; o > 0; o >>= 1) acc += __shfl_xor_sync(0xFFFFFFFFu, acc, o);
    if ((threadIdx.x & 31) == 0) red[threadIdx.x >> 5] = acc;
    __syncthreads();
    if (threadIdx.x == 0) {
        float s = 0.f;
        #pragma unroll
        for (int w = 0; w < 8; w++) s += red[w];
        out[b] = s + g_bias_sum;
    }
}

// ---------------------------------------------------------------------------
// Launch: zero -> wsum -> bias -> dot (default stream, sequential, capturable)
// Inputs (metadata order): d_in[0]=x [2048*8192 f32], d_in[1]=weight
// [8192*8192 f32], d_in[2]=bias [8192 f32]. Output: 2048 f32.
// ---------------------------------------------------------------------------
extern "C" void kernel_launch(void* const* d_in, const int* in_sizes, int n_in,
                              void* d_out, int out_size) {
    const float4* x = (const float4*)d_in[0];
    const float4* w = (const float4*)d_in[1];
    const float4* bias = (const float4*)d_in[2];
    float* out = (float*)d_out;

    zero_kernel<<<8, 256>>>();
    dim3 g1(8, 8192 / ROWS_PER);              // 8 x 128 = 1024 blocks
    wsum_kernel<<<g1, 256>>>(w);
    bias_kernel<<<1, 256>>>(bias);
    dot_kernel<<<2048, 256>>>(x, out);
}

// round 2
// speedup vs baseline: 1.0245x; 1.0245x over previous
#include <cuda_runtime.h>
#include <cuda_bf16.h>

// Scratch (no cudaMalloc allowed).
// Partial column sums: 64 row-chunks x 8192 cols (as float4) = 2 MB.
#define NCHUNKS 64
#define ROWS_PER 128           // 64 * 128 = 8192 rows
__device__ float4 g_part[NCHUNKS * 2048];
__device__ float4 g_wsum4[2048];   // final column sums (8192 floats)
__device__ float  g_bias_sum;

// ---------------------------------------------------------------------------
// Kernel 1: partial column sums of weight, pure stores (deterministic, no
// atomics, no zeroing pass). grid = (8, 64), block = 256.
// Block (bx, by): columns [bx*1024, bx*1024+1024), rows [by*128, by*128+128).
// Per row the block loads 4 KB contiguous (256 x float4) -> fully coalesced.
// 4 accumulators + unroll 2 over a 4-row step -> 8 loads in flight, ~56 regs.
// __ldcs: weight has zero reuse, keep it out of L2's way.
// ---------------------------------------------------------------------------
__global__ void __launch_bounds__(256) wsum_kernel(const float4* __restrict__ w) {
    const int col4 = blockIdx.x * 256 + threadIdx.x;        // 0..2047
    const size_t row0 = (size_t)blockIdx.y * ROWS_PER;
    const float4* p = w + row0 * 2048 + col4;

    float4 a0 = make_float4(0.f, 0.f, 0.f, 0.f);
    float4 a1 = make_float4(0.f, 0.f, 0.f, 0.f);
    float4 a2 = make_float4(0.f, 0.f, 0.f, 0.f);
    float4 a3 = make_float4(0.f, 0.f, 0.f, 0.f);

    #pragma unroll 2
    for (int r = 0; r < ROWS_PER; r += 4) {
        float4 v0 = __ldcs(&p[(size_t)(r + 0) * 2048]);
        float4 v1 = __ldcs(&p[(size_t)(r + 1) * 2048]);
        float4 v2 = __ldcs(&p[(size_t)(r + 2) * 2048]);
        float4 v3 = __ldcs(&p[(size_t)(r + 3) * 2048]);
        a0.x += v0.x; a0.y += v0.y; a0.z += v0.z; a0.w += v0.w;
        a1.x += v1.x; a1.y += v1.y; a1.z += v1.z; a1.w += v1.w;
        a2.x += v2.x; a2.y += v2.y; a2.z += v2.z; a2.w += v2.w;
        a3.x += v3.x; a3.y += v3.y; a3.z += v3.z; a3.w += v3.w;
    }
    float4 s;
    s.x = (a0.x + a1.x) + (a2.x + a3.x);
    s.y = (a0.y + a1.y) + (a2.y + a3.y);
    s.z = (a0.z + a1.z) + (a2.z + a3.z);
    s.w = (a0.w + a1.w) + (a2.w + a3.w);
    g_part[blockIdx.y * 2048 + col4] = s;
}

// ---------------------------------------------------------------------------
// Kernel 2: reduce partials -> g_wsum4, and (block 8) bias -> g_bias_sum.
// grid = 9, block = 256. Partials are L2-hot (2 MB just written).
// ---------------------------------------------------------------------------
__global__ void __launch_bounds__(256) reduce_kernel(const float4* __restrict__ bias4) {
    if (blockIdx.x < 8) {
        const int col4 = blockIdx.x * 256 + threadIdx.x;    // 0..2047
        float4 a = make_float4(0.f, 0.f, 0.f, 0.f);
        #pragma unroll 8
        for (int c = 0; c < NCHUNKS; c++) {
            float4 v = g_part[c * 2048 + col4];
            a.x += v.x; a.y += v.y; a.z += v.z; a.w += v.w;
        }
        g_wsum4[col4] = a;
    } else {
        // bias sum: 8192 floats = 2048 float4, one block
        __shared__ float red[8];
        float acc = 0.f;
        for (int i = threadIdx.x; i < 2048; i += 256) {
            float4 v = bias4[i];
            acc += (v.x + v.y) + (v.z + v.w);
        }
        for (int o = 16; o > 0; o >>= 1) acc += __shfl_xor_sync(0xFFFFFFFFu, acc, o);
        if ((threadIdx.x & 31) == 0) red[threadIdx.x >> 5] = acc;
        __syncthreads();
        if (threadIdx.x == 0) {
            float s = 0.f;
            #pragma unroll
            for (int w = 0; w < 8; w++) s += red[w];
            g_bias_sum = s;
        }
    }
}

// ---------------------------------------------------------------------------
// Kernel 3: out[b] = dot(x[b,:], w_sum) + bias_sum.
// Warp-per-row: no smem, no block sync, warp shuffle reduce only.
// grid = 128 blocks x 512 threads = 16 warps/block -> 2048 rows, single wave.
// Each thread: 64 float4 of x (coalesced 512B/warp/iter) + wsum from L1/L2.
// ---------------------------------------------------------------------------
__global__ void __launch_bounds__(512) dot_kernel(const float4* __restrict__ x,
                                                  float* __restrict__ out) {
    const int warp = threadIdx.x >> 5;
    const int lane = threadIdx.x & 31;
    const int b = blockIdx.x * 16 + warp;                  // 0..2047
    const float4* xr = x + (size_t)b * 2048 + lane;
    const float4* ws = g_wsum4 + lane;

    float ax = 0.f, ay = 0.f, az = 0.f, aw = 0.f;
    #pragma unroll 8
    for (int i = 0; i < 64; i++) {
        float4 xv = __ldcs(&xr[i * 32]);
        float4 wv = ws[i * 32];
        ax += xv.x * wv.x;
        ay += xv.y * wv.y;
        az += xv.z * wv.z;
        aw += xv.w * wv.w;
    }
    float acc = (ax + ay) + (az + aw);
    for (int o = 16; o > 0; o >>= 1) acc += __shfl_xor_sync(0xFFFFFFFFu, acc, o);
    if (lane == 0) out[b] = acc + g_bias_sum;
}

// ---------------------------------------------------------------------------
// 3 launches: wsum -> reduce(+bias) -> dot. All graph-capturable, no allocs.
// Inputs: d_in[0]=x [2048*8192 f32], d_in[1]=weight [8192*8192 f32],
// d_in[2]=bias [8192 f32]. Output: 2048 f32.
// ---------------------------------------------------------------------------
extern "C" void kernel_launch(void* const* d_in, const int* in_sizes, int n_in,
                              void* d_out, int out_size) {
    const float4* x = (const float4*)d_in[0];
    const float4* w = (const float4*)d_in[1];
    const float4* bias = (const float4*)d_in[2];
    float* out = (float*)d_out;

    dim3 g1(8, NCHUNKS);                      // 512 blocks, single wave
    wsum_kernel<<<g1, 256>>>(w);
    reduce_kernel<<<9, 256>>>(bias);
    dot_kernel<<<128, 512>>>(x, out);
}